// round 15
// baseline (speedup 1.0000x reference)
#include <cuda_runtime.h>
#include <cuda_fp16.h>
#include <cstdint>

// Problem dims (fixed by the dataset)
#define S_TOK 8192      // B*T
#define MDIM  1024
#define HDIM  4096
#define ODIM  1024
#define EEXP  4
#define CCAP  2048      // ceil(S/E)

// ---------------- device scratch (no cudaMalloc allowed) ----------------
__device__ __half g_disp [(size_t)EEXP * CCAP * MDIM];   // 16 MB  dispatched tokens (fp16)
__device__ __half g_h    [(size_t)EEXP * CCAP * HDIM];   // 64 MB  fc1 activations (fp16)
__device__ __half g_w1t  [(size_t)EEXP * HDIM * MDIM];   // 32 MB  w1^T [E][H][M] fp16
__device__ __half g_w2t  [(size_t)EEXP * ODIM * HDIM];   // 32 MB  w2^T [E][O][H] fp16
__device__ float  g_probs[S_TOK * 4];
__device__ float  g_gate [S_TOK];
__device__ int    g_eidx [S_TOK];
__device__ int    g_tok_slot[S_TOK];
__device__ int    g_slot_tok[EEXP * CCAP];

// ---------------- helpers ----------------
__device__ __forceinline__ float gelu_tanh(float x) {
    float x3 = x * x * x;
    return 0.5f * x * (1.0f + tanhf(0.7978845608028654f * (x + 0.044715f * x3)));
}

__device__ __forceinline__ uint32_t smem_u32(const void* p) {
    uint32_t a;
    asm("{ .reg .u64 t; cvta.to.shared.u64 t, %1; cvt.u32.u64 %0, t; }" : "=r"(a) : "l"(p));
    return a;
}

__device__ __forceinline__ void cp16(uint32_t s, const void* g) {
    asm volatile("cp.async.cg.shared.global [%0], [%1], 16;\n" :: "r"(s), "l"(g));
}
__device__ __forceinline__ void cp_commit() {
    asm volatile("cp.async.commit_group;\n" ::: "memory");
}
template<int N> __device__ __forceinline__ void cp_wait() {
    asm volatile("cp.async.wait_group %0;\n" :: "n"(N) : "memory");
}

__device__ __forceinline__ void ldsm_x4(uint32_t& r0, uint32_t& r1, uint32_t& r2,
                                        uint32_t& r3, uint32_t addr) {
    asm volatile("ldmatrix.sync.aligned.m8n8.x4.shared.b16 {%0,%1,%2,%3}, [%4];"
                 : "=r"(r0), "=r"(r1), "=r"(r2), "=r"(r3) : "r"(addr));
}

// ---------------- 1. gate (R6 version) ----------------
__global__ void gate_kernel(const float* __restrict__ feats,
                            const float* __restrict__ gw) {
    int gtid = blockIdx.x * blockDim.x + threadIdx.x;
    int tok  = gtid >> 5;
    int lane = threadIdx.x & 31;
    if (tok >= S_TOK) return;

    const float* f = feats + (size_t)tok * MDIM;
    float a0 = 0.f, a1 = 0.f, a2 = 0.f, a3 = 0.f;
    for (int m = lane; m < MDIM; m += 32) {
        float fv = f[m];
        float4 w = __ldg((const float4*)gw + m);
        a0 += fv * w.x; a1 += fv * w.y; a2 += fv * w.z; a3 += fv * w.w;
    }
    #pragma unroll
    for (int o = 16; o; o >>= 1) {
        a0 += __shfl_down_sync(0xffffffffu, a0, o);
        a1 += __shfl_down_sync(0xffffffffu, a1, o);
        a2 += __shfl_down_sync(0xffffffffu, a2, o);
        a3 += __shfl_down_sync(0xffffffffu, a3, o);
    }
    if (lane == 0) {
        float l[4] = {a0, a1, a2, a3};
        float mx = l[0]; int ai = 0;
        #pragma unroll
        for (int e = 1; e < 4; e++) if (l[e] > mx) { mx = l[e]; ai = e; }
        float p[4], s = 0.f;
        #pragma unroll
        for (int e = 0; e < 4; e++) { p[e] = expf(l[e] - mx); s += p[e]; }
        float inv = 1.0f / s;
        ((float4*)g_probs)[tok] = make_float4(p[0]*inv, p[1]*inv, p[2]*inv, p[3]*inv);
        g_eidx[tok] = ai;
        g_gate[tok] = p[ai] * inv;
    }
}

// ---------------- 2. capacity scan (shfl hierarchical, 2 barriers) ---------
__global__ void scan_kernel() {
    __shared__ unsigned long long wsum[32];
    int tid  = threadIdx.x;
    int lane = tid & 31, warp = tid >> 5;

    for (int i = tid; i < EEXP * CCAP; i += 1024) g_slot_tok[i] = -1;

    int el[8];
    unsigned long long cnt = 0ull;
    #pragma unroll
    for (int j = 0; j < 8; j++) {
        int e = g_eidx[tid * 8 + j];
        el[j] = e;
        cnt += 1ull << (e * 16);
    }

    unsigned long long incl = cnt;
    #pragma unroll
    for (int o = 1; o < 32; o <<= 1) {
        unsigned long long v = __shfl_up_sync(0xffffffffu, incl, o);
        if (lane >= o) incl += v;
    }
    if (lane == 31) wsum[warp] = incl;
    __syncthreads();

    if (warp == 0) {
        unsigned long long w = wsum[lane];
        unsigned long long wi = w;
        #pragma unroll
        for (int o = 1; o < 32; o <<= 1) {
            unsigned long long v = __shfl_up_sync(0xffffffffu, wi, o);
            if (lane >= o) wi += v;
        }
        wsum[lane] = wi - w;   // exclusive
    }
    __syncthreads();

    unsigned long long base = wsum[warp] + (incl - cnt);
    #pragma unroll
    for (int j = 0; j < 8; j++) {
        int e   = el[j];
        int pos = (int)((base >> (e * 16)) & 0xFFFFull);
        int tok = tid * 8 + j;
        if (pos < CCAP) {
            int slot = e * CCAP + pos;
            g_tok_slot[tok]  = slot;
            g_slot_tok[slot] = tok;
        } else {
            g_tok_slot[tok] = -1;
        }
        base += 1ull << (e * 16);
    }
}

// ---------------- 3. gather (fp16) + zero dropped output rows --------------
// blockIdx.x plays two roles: slot id (gather into g_disp) and token id
// (zero out[token] if that token was dropped). Both grids are 8192.
__global__ void gather_zero_kernel(const float* __restrict__ feats,
                                   float* __restrict__ out) {
    int slot = blockIdx.x;
    int t    = threadIdx.x;                 // 256 threads
    int tok  = g_slot_tok[slot];
    uint2* d = (uint2*)(g_disp + (size_t)slot * MDIM) + t;
    if (tok < 0) {
        *d = make_uint2(0u, 0u);
    } else {
        float4 v = ((const float4*)(feats + (size_t)tok * MDIM))[t];
        __half2 h0 = __floats2half2_rn(v.x, v.y);
        __half2 h1 = __floats2half2_rn(v.z, v.w);
        *d = make_uint2(*(uint32_t*)&h0, *(uint32_t*)&h1);
    }
    // zero role: token = blockIdx.x (S_TOK == EEXP*CCAP == 8192)
    int tok2 = blockIdx.x;
    if (g_tok_slot[tok2] < 0) {
        ((float4*)(out + (size_t)tok2 * ODIM))[t] =
            make_float4(0.f, 0.f, 0.f, 0.f);  // 256 * 16B = ODIM floats
    }
}

// ---------------- 3c. weight transpose+convert [E][K][N]f32 -> [E][N][K]f16
// 128(N) x 64(K) tiles: 2x work per barrier vs 64x64; uint2 (4-half) stores.
__global__ void transpose_kernel(const float* __restrict__ w, __half* __restrict__ wt,
                                 int K, int N) {
    __shared__ float ts[64][129];
    int e  = blockIdx.z;
    int k0 = blockIdx.y * 64, n0 = blockIdx.x * 128;
    const float* we = w  + (size_t)e * K * N;
    __half*     wte = wt + (size_t)e * K * N;
    int tid = threadIdx.x;   // 256

    // phase 1: load 64 k-rows x 128 n-cols (float4, fully coalesced)
    #pragma unroll
    for (int i = 0; i < 8; i++) {
        int idx = tid + i * 256;
        int r = idx >> 5, c4 = (idx & 31) * 4;
        float4 v = *(const float4*)(we + (size_t)(k0 + r) * N + n0 + c4);
        ts[r][c4 + 0] = v.x; ts[r][c4 + 1] = v.y;
        ts[r][c4 + 2] = v.z; ts[r][c4 + 3] = v.w;
    }
    __syncthreads();
    // phase 2: write 128 n-rows x 64 k (uint2 = 4 halves, 128B segments)
    #pragma unroll
    for (int i = 0; i < 8; i++) {
        int idx = tid + i * 256;
        int n = idx >> 4, kq = idx & 15;        // kq: group of 4 k-values
        __half2 h0 = __floats2half2_rn(ts[4 * kq + 0][n], ts[4 * kq + 1][n]);
        __half2 h1 = __floats2half2_rn(ts[4 * kq + 2][n], ts[4 * kq + 3][n]);
        uint2 u = make_uint2(*(uint32_t*)&h0, *(uint32_t*)&h1);
        *(uint2*)(wte + (size_t)(n0 + n) * K + k0 + 4 * kq) = u;
    }
}

// ---------------- 4/5. grouped GEMM: fp16 mma + ldmatrix (R6 config) -------
#define GBM 128
#define GBN 128
#define GBK 32
#define NSTAGE 4
#define SAH 40                           // halves per A row (32 + pad 8) = 80 B
#define SBH 40                           // halves per B row
#define SA_HALF (GBM * SAH)              // 5120 halves = 10240 B
#define SB_HALF (GBN * SBH)              // 5120 halves = 10240 B
#define SMEM_BYTES (NSTAGE * (SA_HALF + SB_HALF) * 2)   // 81920 B -> 2 CTAs/SM

template <bool PHASE1>
__global__ void __launch_bounds__(128, 2) moe_gemm(const __half* __restrict__ Ball,
                                                   const float* __restrict__ biasAll,
                                                   float* __restrict__ outp) {
    constexpr int K  = PHASE1 ? MDIM : HDIM;
    constexpr int N  = PHASE1 ? HDIM : ODIM;
    constexpr int KT = K / GBK;

    extern __shared__ __half smem[];

    const __half* Aall = PHASE1 ? g_disp : g_h;

    const int e = blockIdx.z;
    const __half* A    = Aall    + (size_t)e * CCAP * K;
    const __half* B    = Ball    + (size_t)e * (size_t)N * K;   // [N][K] half
    const float*  bias = biasAll + (size_t)e * N;

    const int tid  = threadIdx.x;
    const int warp = tid >> 5, lane = tid & 31;
    const int wm = warp >> 1, wn = warp & 1;      // 2x2 warp grid, warp tile 64x64
    const int g  = lane >> 2, tg = lane & 3;
    const int rowBase = blockIdx.y * GBM;
    const int colBase = blockIdx.x * GBN;

    const __half* Ag = A + (size_t)rowBase * K;
    const __half* Bg = B + (size_t)colBase * K;

    const uint32_t sb = smem_u32(smem);

    const int l_r  = tid >> 2;            // 0..31 (+32*i, 4 iters)
    const int l_kc = (tid & 3) * 8;       // 0,8,16,24 halves

    auto load_tile = [&](int kt, int stage) {
        const int k0 = kt * GBK;
        uint32_t sA = sb + (stage * SA_HALF) * 2;
        uint32_t sB = sb + (NSTAGE * SA_HALF + stage * SB_HALF) * 2;
        #pragma unroll
        for (int i = 0; i < 4; i++) {
            int r = l_r + i * 32;
            cp16(sA + (r * SAH + l_kc) * 2, Ag + (size_t)r * K + k0 + l_kc);
        }
        #pragma unroll
        for (int i = 0; i < 4; i++) {
            int r = l_r + i * 32;
            cp16(sB + (r * SBH + l_kc) * 2, Bg + (size_t)r * K + k0 + l_kc);
        }
    };

    uint32_t offA[4], offB[4];
    #pragma unroll
    for (int mt = 0; mt < 4; mt++)
        offA[mt] = ((wm * 64 + mt * 16 + (lane & 15)) * SAH + ((lane >> 4) << 3)) * 2;
    #pragma unroll
    for (int p = 0; p < 4; p++) {
        int n_off = p * 16 + ((lane >> 4) << 3) + (lane & 7);
        offB[p] = ((wn * 64 + n_off) * SBH + (((lane >> 3) & 1) << 3)) * 2;
    }

    float acc[4][8][4];
    #pragma unroll
    for (int i = 0; i < 4; i++)
        #pragma unroll
        for (int j = 0; j < 8; j++)
            #pragma unroll
            for (int r = 0; r < 4; r++) acc[i][j][r] = 0.f;

    load_tile(0, 0); cp_commit();
    load_tile(1, 1); cp_commit();
    load_tile(2, 2); cp_commit();

    for (int kt = 0; kt < KT; kt++) {
        const int stage = kt & (NSTAGE - 1);
        cp_wait<2>();
        __syncthreads();

        const uint32_t sA = sb + (stage * SA_HALF) * 2;
        const uint32_t sB = sb + (NSTAGE * SA_HALF + stage * SB_HALF) * 2;

        #pragma unroll
        for (int ks = 0; ks < 2; ks++) {
            const uint32_t kb = ks * 32;
            uint32_t af[4][4], bf[8][2];
            #pragma unroll
            for (int mt = 0; mt < 4; mt++)
                ldsm_x4(af[mt][0], af[mt][1], af[mt][2], af[mt][3],
                        sA + offA[mt] + kb);
            #pragma unroll
            for (int p = 0; p < 4; p++)
                ldsm_x4(bf[2*p][0], bf[2*p][1], bf[2*p+1][0], bf[2*p+1][1],
                        sB + offB[p] + kb);
            #pragma unroll
            for (int mt = 0; mt < 4; mt++)
                #pragma unroll
                for (int nt = 0; nt < 8; nt++) {
                    asm volatile(
                        "mma.sync.aligned.m16n8k16.row.col.f32.f16.f16.f32 "
                        "{%0,%1,%2,%3}, {%4,%5,%6,%7}, {%8,%9}, {%0,%1,%2,%3};\n"
                        : "+f"(acc[mt][nt][0]), "+f"(acc[mt][nt][1]),
                          "+f"(acc[mt][nt][2]), "+f"(acc[mt][nt][3])
                        : "r"(af[mt][0]), "r"(af[mt][1]), "r"(af[mt][2]), "r"(af[mt][3]),
                          "r"(bf[nt][0]), "r"(bf[nt][1]));
                }
        }

        if (kt + 3 < KT) load_tile(kt + 3, (kt + 3) & (NSTAGE - 1));
        cp_commit();
    }

    // epilogue
    #pragma unroll
    for (int mt = 0; mt < 4; mt++) {
        int r0 = rowBase + wm * 64 + mt * 16 + g;
        if (PHASE1) {
            __half* Ch = g_h + (size_t)e * CCAP * N;
            #pragma unroll
            for (int nt = 0; nt < 8; nt++) {
                int c0 = colBase + wn * 64 + nt * 8 + tg * 2;
                float b0 = __ldg(bias + c0), b1 = __ldg(bias + c0 + 1);
                __half2 h01 = __floats2half2_rn(gelu_tanh(acc[mt][nt][0] + b0),
                                                gelu_tanh(acc[mt][nt][1] + b1));
                __half2 h23 = __floats2half2_rn(gelu_tanh(acc[mt][nt][2] + b0),
                                                gelu_tanh(acc[mt][nt][3] + b1));
                *(__half2*)&Ch[(size_t)r0       * N + c0] = h01;
                *(__half2*)&Ch[(size_t)(r0 + 8) * N + c0] = h23;
            }
        } else {
            // fused combine: scatter gate * (acc + bias) to out[token]
            int tokA = g_slot_tok[e * CCAP + r0];
            int tokB = g_slot_tok[e * CCAP + r0 + 8];
            float gvA = (tokA >= 0) ? g_gate[tokA] : 0.f;
            float gvB = (tokB >= 0) ? g_gate[tokB] : 0.f;
            float* oA = outp + (size_t)tokA * ODIM;
            float* oB = outp + (size_t)tokB * ODIM;
            #pragma unroll
            for (int nt = 0; nt < 8; nt++) {
                int c0 = colBase + wn * 64 + nt * 8 + tg * 2;
                float b0 = __ldg(bias + c0), b1 = __ldg(bias + c0 + 1);
                if (tokA >= 0)
                    *(float2*)&oA[c0] = make_float2(gvA * (acc[mt][nt][0] + b0),
                                                    gvA * (acc[mt][nt][1] + b1));
                if (tokB >= 0)
                    *(float2*)&oB[c0] = make_float2(gvB * (acc[mt][nt][2] + b0),
                                                    gvB * (acc[mt][nt][3] + b1));
            }
        }
    }
}

// ---------------- 7. l_aux ----------------
__global__ void laux_kernel(float* __restrict__ out, int out_size) {
    __shared__ float sp[4][256];
    __shared__ float sc[4][256];
    int t = threadIdx.x;
    float p[4] = {0.f, 0.f, 0.f, 0.f};
    float c[4] = {0.f, 0.f, 0.f, 0.f};
    for (int s = t; s < S_TOK; s += 256) {
        float4 pr = ((const float4*)g_probs)[s];
        p[0] += pr.x; p[1] += pr.y; p[2] += pr.z; p[3] += pr.w;
        int e = g_eidx[s];
        #pragma unroll
        for (int k = 0; k < 4; k++) c[k] += (e == k) ? 1.f : 0.f;
    }
    #pragma unroll
    for (int k = 0; k < 4; k++) { sp[k][t] = p[k]; sc[k][t] = c[k]; }
    __syncthreads();
    for (int off = 128; off; off >>= 1) {
        if (t < off) {
            #pragma unroll
            for (int k = 0; k < 4; k++) {
                sp[k][t] += sp[k][t + off];
                sc[k][t] += sc[k][t + off];
            }
        }
        __syncthreads();
    }
    if (t == 0 && out_size > S_TOK * ODIM) {
        float inv = 1.0f / (float)S_TOK;
        float l = 0.f;
        #pragma unroll
        for (int k = 0; k < 4; k++) l += (sp[k][0] * inv) * (sc[k][0] * inv);
        out[(size_t)S_TOK * ODIM] = l * (float)EEXP;
    }
}

// ---------------- launch (single stream) ----------------
extern "C" void kernel_launch(void* const* d_in, const int* in_sizes, int n_in,
                              void* d_out, int out_size) {
    (void)in_sizes; (void)n_in;
    const float* hs = (const float*)d_in[0];   // [8,1024,1024]
    const float* gw = (const float*)d_in[1];   // [1024,4]
    const float* w1 = (const float*)d_in[2];   // [4,1024,4096]
    const float* b1 = (const float*)d_in[3];   // [4,4096]
    const float* w2 = (const float*)d_in[4];   // [4,4096,1024]
    const float* b2 = (const float*)d_in[5];   // [4,1024]
    float* out = (float*)d_out;

    cudaFuncSetAttribute(moe_gemm<true>,
                         cudaFuncAttributeMaxDynamicSharedMemorySize, SMEM_BYTES);
    cudaFuncSetAttribute(moe_gemm<false>,
                         cudaFuncAttributeMaxDynamicSharedMemorySize, SMEM_BYTES);

    __half* w1t; cudaGetSymbolAddress((void**)&w1t, g_w1t);
    __half* w2t; cudaGetSymbolAddress((void**)&w2t, g_w2t);

    gate_kernel<<<S_TOK / 8, 256>>>(hs, gw);
    scan_kernel<<<1, 1024>>>();
    gather_zero_kernel<<<EEXP * CCAP, 256>>>(hs, out);
    transpose_kernel<<<dim3(HDIM / 128, MDIM / 64, EEXP), 256>>>(w1, w1t, MDIM, HDIM);
    transpose_kernel<<<dim3(ODIM / 128, HDIM / 64, EEXP), 256>>>(w2, w2t, HDIM, ODIM);
    moe_gemm<true ><<<dim3(HDIM / GBN, CCAP / GBM, EEXP), 128, SMEM_BYTES>>>(w1t, b1, out);
    moe_gemm<false><<<dim3(ODIM / GBN, CCAP / GBM, EEXP), 128, SMEM_BYTES>>>(w2t, b2, out);
    laux_kernel<<<1, 256>>>(out, out_size);
}

// round 16
// speedup vs baseline: 1.0241x; 1.0241x over previous
#include <cuda_runtime.h>
#include <cuda_fp16.h>
#include <cstdint>

// Problem dims (fixed by the dataset)
#define S_TOK 8192      // B*T
#define MDIM  1024
#define HDIM  4096
#define ODIM  1024
#define EEXP  4
#define CCAP  2048      // ceil(S/E)

// ---------------- device scratch (no cudaMalloc allowed) ----------------
__device__ __half g_disp [(size_t)EEXP * CCAP * MDIM];   // 16 MB  dispatched tokens (fp16)
__device__ __half g_h    [(size_t)EEXP * CCAP * HDIM];   // 64 MB  fc1 activations (fp16)
__device__ __half g_w1t  [(size_t)EEXP * HDIM * MDIM];   // 32 MB  w1^T [E][H][M] fp16
__device__ __half g_w2t  [(size_t)EEXP * ODIM * HDIM];   // 32 MB  w2^T [E][O][H] fp16
__device__ float  g_probs[S_TOK * 4];
__device__ float  g_gate [S_TOK];
__device__ int    g_eidx [S_TOK];
__device__ int    g_tok_slot[S_TOK];
__device__ int    g_slot_tok[EEXP * CCAP];

// ---------------- helpers ----------------
__device__ __forceinline__ float gelu_tanh(float x) {
    float x3 = x * x * x;
    return 0.5f * x * (1.0f + tanhf(0.7978845608028654f * (x + 0.044715f * x3)));
}

__device__ __forceinline__ uint32_t smem_u32(const void* p) {
    uint32_t a;
    asm("{ .reg .u64 t; cvta.to.shared.u64 t, %1; cvt.u32.u64 %0, t; }" : "=r"(a) : "l"(p));
    return a;
}

__device__ __forceinline__ void cp16(uint32_t s, const void* g) {
    asm volatile("cp.async.cg.shared.global [%0], [%1], 16;\n" :: "r"(s), "l"(g));
}
__device__ __forceinline__ void cp_commit() {
    asm volatile("cp.async.commit_group;\n" ::: "memory");
}
template<int N> __device__ __forceinline__ void cp_wait() {
    asm volatile("cp.async.wait_group %0;\n" :: "n"(N) : "memory");
}

__device__ __forceinline__ void ldsm_x4(uint32_t& r0, uint32_t& r1, uint32_t& r2,
                                        uint32_t& r3, uint32_t addr) {
    asm volatile("ldmatrix.sync.aligned.m8n8.x4.shared.b16 {%0,%1,%2,%3}, [%4];"
                 : "=r"(r0), "=r"(r1), "=r"(r2), "=r"(r3) : "r"(addr));
}

// ---------------- 1. gate (R6 version) ----------------
__global__ void gate_kernel(const float* __restrict__ feats,
                            const float* __restrict__ gw) {
    int gtid = blockIdx.x * blockDim.x + threadIdx.x;
    int tok  = gtid >> 5;
    int lane = threadIdx.x & 31;
    if (tok >= S_TOK) return;

    const float* f = feats + (size_t)tok * MDIM;
    float a0 = 0.f, a1 = 0.f, a2 = 0.f, a3 = 0.f;
    for (int m = lane; m < MDIM; m += 32) {
        float fv = f[m];
        float4 w = __ldg((const float4*)gw + m);
        a0 += fv * w.x; a1 += fv * w.y; a2 += fv * w.z; a3 += fv * w.w;
    }
    #pragma unroll
    for (int o = 16; o; o >>= 1) {
        a0 += __shfl_down_sync(0xffffffffu, a0, o);
        a1 += __shfl_down_sync(0xffffffffu, a1, o);
        a2 += __shfl_down_sync(0xffffffffu, a2, o);
        a3 += __shfl_down_sync(0xffffffffu, a3, o);
    }
    if (lane == 0) {
        float l[4] = {a0, a1, a2, a3};
        float mx = l[0]; int ai = 0;
        #pragma unroll
        for (int e = 1; e < 4; e++) if (l[e] > mx) { mx = l[e]; ai = e; }
        float p[4], s = 0.f;
        #pragma unroll
        for (int e = 0; e < 4; e++) { p[e] = expf(l[e] - mx); s += p[e]; }
        float inv = 1.0f / s;
        ((float4*)g_probs)[tok] = make_float4(p[0]*inv, p[1]*inv, p[2]*inv, p[3]*inv);
        g_eidx[tok] = ai;
        g_gate[tok] = p[ai] * inv;
    }
}

// ---------------- 2. capacity scan (shfl hierarchical, 2 barriers) ---------
__global__ void scan_kernel() {
    __shared__ unsigned long long wsum[32];
    int tid  = threadIdx.x;
    int lane = tid & 31, warp = tid >> 5;

    for (int i = tid; i < EEXP * CCAP; i += 1024) g_slot_tok[i] = -1;

    int el[8];
    unsigned long long cnt = 0ull;
    #pragma unroll
    for (int j = 0; j < 8; j++) {
        int e = g_eidx[tid * 8 + j];
        el[j] = e;
        cnt += 1ull << (e * 16);
    }

    unsigned long long incl = cnt;
    #pragma unroll
    for (int o = 1; o < 32; o <<= 1) {
        unsigned long long v = __shfl_up_sync(0xffffffffu, incl, o);
        if (lane >= o) incl += v;
    }
    if (lane == 31) wsum[warp] = incl;
    __syncthreads();

    if (warp == 0) {
        unsigned long long w = wsum[lane];
        unsigned long long wi = w;
        #pragma unroll
        for (int o = 1; o < 32; o <<= 1) {
            unsigned long long v = __shfl_up_sync(0xffffffffu, wi, o);
            if (lane >= o) wi += v;
        }
        wsum[lane] = wi - w;   // exclusive
    }
    __syncthreads();

    unsigned long long base = wsum[warp] + (incl - cnt);
    #pragma unroll
    for (int j = 0; j < 8; j++) {
        int e   = el[j];
        int pos = (int)((base >> (e * 16)) & 0xFFFFull);
        int tok = tid * 8 + j;
        if (pos < CCAP) {
            int slot = e * CCAP + pos;
            g_tok_slot[tok]  = slot;
            g_slot_tok[slot] = tok;
        } else {
            g_tok_slot[tok] = -1;
        }
        base += 1ull << (e * 16);
    }
}

// ---------------- 3. gather (fp16) ----------------
__global__ void gather_kernel(const float* __restrict__ feats) {
    int slot = blockIdx.x;
    int t    = threadIdx.x;                 // 256 threads, 4 halves each (M=1024)
    int tok  = g_slot_tok[slot];
    uint2* d = (uint2*)(g_disp + (size_t)slot * MDIM) + t;
    if (tok < 0) {
        *d = make_uint2(0u, 0u);
    } else {
        float4 v = ((const float4*)(feats + (size_t)tok * MDIM))[t];
        __half2 h0 = __floats2half2_rn(v.x, v.y);
        __half2 h1 = __floats2half2_rn(v.z, v.w);
        *d = make_uint2(*(uint32_t*)&h0, *(uint32_t*)&h1);
    }
}

// ---------------- 3b. zero output rows of dropped tokens -------------------
__global__ void zero_dropped(float* __restrict__ out) {
    int tok  = blockIdx.x * 8 + (threadIdx.x >> 5);
    int lane = threadIdx.x & 31;
    if (g_tok_slot[tok] >= 0) return;
    float4* o = (float4*)(out + (size_t)tok * ODIM);
    #pragma unroll
    for (int i = 0; i < 8; i++)
        o[lane + i * 32] = make_float4(0.f, 0.f, 0.f, 0.f);
}

// ---------------- 3c. both weight transposes in ONE launch -----------------
// Identical 64x64 tile body as the measured-best R13 transpose; blockIdx.z
// selects expert (z&3) and weight tensor (z>>2). w2's (16x64) tile grid is
// remapped onto the (64,16) launch grid.
__global__ void transpose_both_kernel(const float* __restrict__ w1, __half* __restrict__ w1t,
                                      const float* __restrict__ w2, __half* __restrict__ w2t) {
    __shared__ float ts[64][65];
    int z = blockIdx.z;
    int e = z & 3, which = z >> 2;

    const float* w; __half* wt; int K, N, k0, n0;
    if (which == 0) {
        w = w1; wt = w1t; K = MDIM; N = HDIM;             // tiles: n 64 x k 16
        n0 = blockIdx.x * 64; k0 = blockIdx.y * 64;
    } else {
        w = w2; wt = w2t; K = HDIM; N = ODIM;             // tiles: n 16 x k 64
        n0 = (blockIdx.x & 15) * 64;
        k0 = (blockIdx.y * 4 + (blockIdx.x >> 4)) * 64;
    }

    const float* we = w  + (size_t)e * K * N;
    __half*     wte = wt + (size_t)e * K * N;
    int tid = threadIdx.x;   // 256

    #pragma unroll
    for (int i = 0; i < 4; i++) {
        int idx = tid + i * 256;
        int r = idx >> 4, c4 = (idx & 15) * 4;
        float4 v = *(const float4*)(we + (size_t)(k0 + r) * N + n0 + c4);
        ts[r][c4 + 0] = v.x; ts[r][c4 + 1] = v.y;
        ts[r][c4 + 2] = v.z; ts[r][c4 + 3] = v.w;
    }
    __syncthreads();
    #pragma unroll
    for (int i = 0; i < 8; i++) {
        int idx = tid + i * 256;
        int n = idx >> 5, kp = idx & 31;
        __half2 h = __floats2half2_rn(ts[2 * kp][n], ts[2 * kp + 1][n]);
        *(__half2*)(wte + (size_t)(n0 + n) * K + k0 + 2 * kp) = h;
    }
}

// ---------------- 4/5. grouped GEMM: fp16 mma + ldmatrix (R6 config) -------
// CTA tile 128x128, 4 warps, warp tile 64x64 (2x2). 4-stage cp.async, GBK=32.
// A [m][k], B [n][k] half tiles, stride 40 halves (80B): 80*{0..7} mod 128
// is a 16B-bank permutation -> LDSM conflict-free.
// PHASE1: g_disp[2048,1024]h @ w1t -> gelu -> g_h (h)
// else  : g_h  [2048,4096]h @ w2t -> gate-scatter -> out (f32) [fused combine]
#define GBM 128
#define GBN 128
#define GBK 32
#define NSTAGE 4
#define SAH 40                           // halves per A row (32 + pad 8) = 80 B
#define SBH 40                           // halves per B row
#define SA_HALF (GBM * SAH)              // 5120 halves = 10240 B
#define SB_HALF (GBN * SBH)              // 5120 halves = 10240 B
#define SMEM_BYTES (NSTAGE * (SA_HALF + SB_HALF) * 2)   // 81920 B -> 2 CTAs/SM

template <bool PHASE1>
__global__ void __launch_bounds__(128, 2) moe_gemm(const __half* __restrict__ Ball,
                                                   const float* __restrict__ biasAll,
                                                   float* __restrict__ outp) {
    constexpr int K  = PHASE1 ? MDIM : HDIM;
    constexpr int N  = PHASE1 ? HDIM : ODIM;
    constexpr int KT = K / GBK;

    extern __shared__ __half smem[];

    const __half* Aall = PHASE1 ? g_disp : g_h;

    const int e = blockIdx.z;
    const __half* A    = Aall    + (size_t)e * CCAP * K;
    const __half* B    = Ball    + (size_t)e * (size_t)N * K;   // [N][K] half
    const float*  bias = biasAll + (size_t)e * N;

    const int tid  = threadIdx.x;
    const int warp = tid >> 5, lane = tid & 31;
    const int wm = warp >> 1, wn = warp & 1;      // 2x2 warp grid, warp tile 64x64
    const int g  = lane >> 2, tg = lane & 3;
    const int rowBase = blockIdx.y * GBM;
    const int colBase = blockIdx.x * GBN;

    const __half* Ag = A + (size_t)rowBase * K;
    const __half* Bg = B + (size_t)colBase * K;

    const uint32_t sb = smem_u32(smem);

    const int l_r  = tid >> 2;            // 0..31 (+32*i, 4 iters)
    const int l_kc = (tid & 3) * 8;       // 0,8,16,24 halves

    auto load_tile = [&](int kt, int stage) {
        const int k0 = kt * GBK;
        uint32_t sA = sb + (stage * SA_HALF) * 2;
        uint32_t sB = sb + (NSTAGE * SA_HALF + stage * SB_HALF) * 2;
        #pragma unroll
        for (int i = 0; i < 4; i++) {
            int r = l_r + i * 32;
            cp16(sA + (r * SAH + l_kc) * 2, Ag + (size_t)r * K + k0 + l_kc);
        }
        #pragma unroll
        for (int i = 0; i < 4; i++) {
            int r = l_r + i * 32;
            cp16(sB + (r * SBH + l_kc) * 2, Bg + (size_t)r * K + k0 + l_kc);
        }
    };

    uint32_t offA[4], offB[4];
    #pragma unroll
    for (int mt = 0; mt < 4; mt++)
        offA[mt] = ((wm * 64 + mt * 16 + (lane & 15)) * SAH + ((lane >> 4) << 3)) * 2;
    #pragma unroll
    for (int p = 0; p < 4; p++) {
        int n_off = p * 16 + ((lane >> 4) << 3) + (lane & 7);
        offB[p] = ((wn * 64 + n_off) * SBH + (((lane >> 3) & 1) << 3)) * 2;
    }

    float acc[4][8][4];
    #pragma unroll
    for (int i = 0; i < 4; i++)
        #pragma unroll
        for (int j = 0; j < 8; j++)
            #pragma unroll
            for (int r = 0; r < 4; r++) acc[i][j][r] = 0.f;

    load_tile(0, 0); cp_commit();
    load_tile(1, 1); cp_commit();
    load_tile(2, 2); cp_commit();

    for (int kt = 0; kt < KT; kt++) {
        const int stage = kt & (NSTAGE - 1);
        cp_wait<2>();
        __syncthreads();

        const uint32_t sA = sb + (stage * SA_HALF) * 2;
        const uint32_t sB = sb + (NSTAGE * SA_HALF + stage * SB_HALF) * 2;

        #pragma unroll
        for (int ks = 0; ks < 2; ks++) {
            const uint32_t kb = ks * 32;
            uint32_t af[4][4], bf[8][2];
            #pragma unroll
            for (int mt = 0; mt < 4; mt++)
                ldsm_x4(af[mt][0], af[mt][1], af[mt][2], af[mt][3],
                        sA + offA[mt] + kb);
            #pragma unroll
            for (int p = 0; p < 4; p++)
                ldsm_x4(bf[2*p][0], bf[2*p][1], bf[2*p+1][0], bf[2*p+1][1],
                        sB + offB[p] + kb);
            #pragma unroll
            for (int mt = 0; mt < 4; mt++)
                #pragma unroll
                for (int nt = 0; nt < 8; nt++) {
                    asm volatile(
                        "mma.sync.aligned.m16n8k16.row.col.f32.f16.f16.f32 "
                        "{%0,%1,%2,%3}, {%4,%5,%6,%7}, {%8,%9}, {%0,%1,%2,%3};\n"
                        : "+f"(acc[mt][nt][0]), "+f"(acc[mt][nt][1]),
                          "+f"(acc[mt][nt][2]), "+f"(acc[mt][nt][3])
                        : "r"(af[mt][0]), "r"(af[mt][1]), "r"(af[mt][2]), "r"(af[mt][3]),
                          "r"(bf[nt][0]), "r"(bf[nt][1]));
                }
        }

        if (kt + 3 < KT) load_tile(kt + 3, (kt + 3) & (NSTAGE - 1));
        cp_commit();
    }

    // epilogue
    #pragma unroll
    for (int mt = 0; mt < 4; mt++) {
        int r0 = rowBase + wm * 64 + mt * 16 + g;
        if (PHASE1) {
            __half* Ch = g_h + (size_t)e * CCAP * N;
            #pragma unroll
            for (int nt = 0; nt < 8; nt++) {
                int c0 = colBase + wn * 64 + nt * 8 + tg * 2;
                float b0 = __ldg(bias + c0), b1 = __ldg(bias + c0 + 1);
                __half2 h01 = __floats2half2_rn(gelu_tanh(acc[mt][nt][0] + b0),
                                                gelu_tanh(acc[mt][nt][1] + b1));
                __half2 h23 = __floats2half2_rn(gelu_tanh(acc[mt][nt][2] + b0),
                                                gelu_tanh(acc[mt][nt][3] + b1));
                *(__half2*)&Ch[(size_t)r0       * N + c0] = h01;
                *(__half2*)&Ch[(size_t)(r0 + 8) * N + c0] = h23;
            }
        } else {
            // fused combine: scatter gate * (acc + bias) to out[token]
            int tokA = g_slot_tok[e * CCAP + r0];
            int tokB = g_slot_tok[e * CCAP + r0 + 8];
            float gvA = (tokA >= 0) ? g_gate[tokA] : 0.f;
            float gvB = (tokB >= 0) ? g_gate[tokB] : 0.f;
            float* oA = outp + (size_t)tokA * ODIM;
            float* oB = outp + (size_t)tokB * ODIM;
            #pragma unroll
            for (int nt = 0; nt < 8; nt++) {
                int c0 = colBase + wn * 64 + nt * 8 + tg * 2;
                float b0 = __ldg(bias + c0), b1 = __ldg(bias + c0 + 1);
                if (tokA >= 0)
                    *(float2*)&oA[c0] = make_float2(gvA * (acc[mt][nt][0] + b0),
                                                    gvA * (acc[mt][nt][1] + b1));
                if (tokB >= 0)
                    *(float2*)&oB[c0] = make_float2(gvB * (acc[mt][nt][2] + b0),
                                                    gvB * (acc[mt][nt][3] + b1));
            }
        }
    }
}

// ---------------- 7. l_aux ----------------
__global__ void laux_kernel(float* __restrict__ out, int out_size) {
    __shared__ float sp[4][256];
    __shared__ float sc[4][256];
    int t = threadIdx.x;
    float p[4] = {0.f, 0.f, 0.f, 0.f};
    float c[4] = {0.f, 0.f, 0.f, 0.f};
    for (int s = t; s < S_TOK; s += 256) {
        float4 pr = ((const float4*)g_probs)[s];
        p[0] += pr.x; p[1] += pr.y; p[2] += pr.z; p[3] += pr.w;
        int e = g_eidx[s];
        #pragma unroll
        for (int k = 0; k < 4; k++) c[k] += (e == k) ? 1.f : 0.f;
    }
    #pragma unroll
    for (int k = 0; k < 4; k++) { sp[k][t] = p[k]; sc[k][t] = c[k]; }
    __syncthreads();
    for (int off = 128; off; off >>= 1) {
        if (t < off) {
            #pragma unroll
            for (int k = 0; k < 4; k++) {
                sp[k][t] += sp[k][t + off];
                sc[k][t] += sc[k][t + off];
            }
        }
        __syncthreads();
    }
    if (t == 0 && out_size > S_TOK * ODIM) {
        float inv = 1.0f / (float)S_TOK;
        float l = 0.f;
        #pragma unroll
        for (int k = 0; k < 4; k++) l += (sp[k][0] * inv) * (sc[k][0] * inv);
        out[(size_t)S_TOK * ODIM] = l * (float)EEXP;
    }
}

// ---------------- launch (single stream, R13 order; transposes fused) ------
extern "C" void kernel_launch(void* const* d_in, const int* in_sizes, int n_in,
                              void* d_out, int out_size) {
    (void)in_sizes; (void)n_in;
    const float* hs = (const float*)d_in[0];   // [8,1024,1024]
    const float* gw = (const float*)d_in[1];   // [1024,4]
    const float* w1 = (const float*)d_in[2];   // [4,1024,4096]
    const float* b1 = (const float*)d_in[3];   // [4,4096]
    const float* w2 = (const float*)d_in[4];   // [4,4096,1024]
    const float* b2 = (const float*)d_in[5];   // [4,1024]
    float* out = (float*)d_out;

    cudaFuncSetAttribute(moe_gemm<true>,
                         cudaFuncAttributeMaxDynamicSharedMemorySize, SMEM_BYTES);
    cudaFuncSetAttribute(moe_gemm<false>,
                         cudaFuncAttributeMaxDynamicSharedMemorySize, SMEM_BYTES);

    __half* w1t; cudaGetSymbolAddress((void**)&w1t, g_w1t);
    __half* w2t; cudaGetSymbolAddress((void**)&w2t, g_w2t);

    gate_kernel<<<S_TOK / 8, 256>>>(hs, gw);
    scan_kernel<<<1, 1024>>>();
    gather_kernel<<<EEXP * CCAP, 256>>>(hs);
    zero_dropped<<<S_TOK / 8, 256>>>(out);
    transpose_both_kernel<<<dim3(64, 16, 8), 256>>>(w1, w1t, w2, w2t);
    moe_gemm<true ><<<dim3(HDIM / GBN, CCAP / GBM, EEXP), 128, SMEM_BYTES>>>(w1t, b1, out);
    moe_gemm<false><<<dim3(ODIM / GBN, CCAP / GBM, EEXP), 128, SMEM_BYTES>>>(w2t, b2, out);
    laux_kernel<<<1, 256>>>(out, out_size);
}